// round 8
// baseline (speedup 1.0000x reference)
#include <cuda_runtime.h>
#include <cstdint>

// WordEmbedding: out[row, :] = W[ids[row], :]
//   W:   [50257, 1024] float32, ids: [32768] int32, out: [32768, 1024] float32
//
// HBM-bound gather. 8 rows/CTA. asm-volatile loads force ALL 8 LDG.128 to
// issue before any store (ptxas cannot reorder volatile asm), guaranteeing
// MLP=8/thread at the SASS level — plain C code was register-minimized by
// ptxas down to MLP~2-4 (regs=38), leaving DRAM at 64%.

#define DIM 1024
#define VEC_PER_ROW (DIM / 4)   // 256 float4 per row
#define ROWS_PER_CTA 8

__global__ __launch_bounds__(256)
void WordEmbedding_43181601194151_kernel(const float4* __restrict__ w,
                                         const int* __restrict__ ids,
                                         float4* __restrict__ out)
{
    const int base_row = blockIdx.x * ROWS_PER_CTA;
    const int t = threadIdx.x;

    // Vectorized id fetch: 2 LDGs instead of 8 (shorter dependency head)
    const int4* ids4 = (const int4*)(ids + base_row);
    const int4 ia = __ldg(&ids4[0]);
    const int4 ib = __ldg(&ids4[1]);
    const int id[ROWS_PER_CTA] = {ia.x, ia.y, ia.z, ia.w, ib.x, ib.y, ib.z, ib.w};

    // All 8 gather loads issue before any store: volatile asm preserves order.
    float4 v[ROWS_PER_CTA];
#pragma unroll
    for (int r = 0; r < ROWS_PER_CTA; r++) {
        const float4* p = w + (((size_t)id[r]) << 8) + t;
        asm volatile("ld.global.nc.v4.f32 {%0,%1,%2,%3}, [%4];"
                     : "=f"(v[r].x), "=f"(v[r].y), "=f"(v[r].z), "=f"(v[r].w)
                     : "l"(p));
    }

    // Streaming stores: keep L2 for the gathered weight rows.
#pragma unroll
    for (int r = 0; r < ROWS_PER_CTA; r++) {
        float4* q = out + (((size_t)(base_row + r)) << 8) + t;
        asm volatile("st.global.cs.v4.f32 [%0], {%1,%2,%3,%4};"
                     :: "l"(q), "f"(v[r].x), "f"(v[r].y), "f"(v[r].z), "f"(v[r].w)
                     : "memory");
    }
}

extern "C" void kernel_launch(void* const* d_in, const int* in_sizes, int n_in,
                              void* d_out, int out_size)
{
    // Select inputs by size: the weight matrix is by far the larger tensor.
    int w_idx = 0, id_idx = 1;
    if (n_in >= 2 && in_sizes[1] > in_sizes[0]) { w_idx = 1; id_idx = 0; }

    const float4* w   = (const float4*)d_in[w_idx];
    const int*    ids = (const int*)d_in[id_idx];
    float4*       out = (float4*)d_out;

    const int n_rows = out_size / DIM;               // 32768
    const int n_blocks = n_rows / ROWS_PER_CTA;      // 4096

    WordEmbedding_43181601194151_kernel<<<n_blocks, 256>>>(w, ids, out);
}

// round 9
// speedup vs baseline: 1.0309x; 1.0309x over previous
#include <cuda_runtime.h>
#include <cstdint>

// WordEmbedding: out[row, :] = W[ids[row], :]
//   W:   [50257, 1024] fp32 (4KB rows), ids: [32768] int32, out: [32768, 1024] fp32
//
// Pure DMA formulation: TMA bulk copies G->S then S->G, 8 rows (32KB) per CTA.
// The SM-side LDG/STG path plateaued at ~5.2TB/s across 3 variants with all
// pipes <10% busy; the TMA engine has no register/issue/MLP constraints.

#define ROW_BYTES 4096
#define ROWS_PER_CTA 8
#define TILE_BYTES (ROWS_PER_CTA * ROW_BYTES)

__device__ __forceinline__ uint32_t smem_u32(const void* p) {
    uint32_t a;
    asm("{ .reg .u64 t; cvta.to.shared.u64 t, %1; cvt.u32.u64 %0, t; }"
        : "=r"(a) : "l"(p));
    return a;
}

__global__ __launch_bounds__(32)
void WordEmbedding_43181601194151_kernel(const char* __restrict__ w,
                                         const int* __restrict__ ids,
                                         char* __restrict__ out)
{
    __shared__ alignas(128) char buf[TILE_BYTES];
    __shared__ alignas(8) unsigned long long mbar;

    const int base_row = blockIdx.x * ROWS_PER_CTA;

    if (threadIdx.x == 0) {
        const uint32_t mbar_a = smem_u32(&mbar);
        const uint32_t buf_a  = smem_u32(buf);

        // mbarrier init (generic proxy) must be fenced before async-proxy use.
        asm volatile("mbarrier.init.shared.b64 [%0], 1;" :: "r"(mbar_a) : "memory");
        asm volatile("fence.proxy.async.shared::cta;" ::: "memory");
        asm volatile("mbarrier.arrive.expect_tx.shared.b64 _, [%0], %1;"
                     :: "r"(mbar_a), "r"((uint32_t)TILE_BYTES) : "memory");

        // Fetch 8 ids (2x int4)
        const int4* ids4 = (const int4*)(ids + base_row);
        const int4 ia = __ldg(&ids4[0]);
        const int4 ib = __ldg(&ids4[1]);
        const int id[ROWS_PER_CTA] = {ia.x, ia.y, ia.z, ia.w, ib.x, ib.y, ib.z, ib.w};

        // 8 async bulk gathers G->S, completion counted on the mbarrier.
#pragma unroll
        for (int r = 0; r < ROWS_PER_CTA; r++) {
            const char* src = w + (size_t)id[r] * ROW_BYTES;
            asm volatile(
                "cp.async.bulk.shared::cluster.global.mbarrier::complete_tx::bytes "
                "[%0], [%1], %2, [%3];"
                :: "r"(buf_a + r * ROW_BYTES), "l"(src), "r"((uint32_t)ROW_BYTES),
                   "r"(mbar_a)
                : "memory");
        }

        // Wait for all 32KB to land.
        {
            uint32_t done;
            asm volatile(
                "{\n\t.reg .pred p;\n\t"
                "mbarrier.try_wait.parity.shared.b64 p, [%1], 0;\n\t"
                "selp.b32 %0, 1, 0, p;\n\t}"
                : "=r"(done) : "r"(mbar_a) : "memory");
            while (!done) {
                asm volatile(
                    "{\n\t.reg .pred p;\n\t"
                    "mbarrier.try_wait.parity.shared.b64 p, [%1], 0, 10000000;\n\t"
                    "selp.b32 %0, 1, 0, p;\n\t}"
                    : "=r"(done) : "r"(mbar_a) : "memory");
            }
        }

        // evict_first policy for the streaming output: keep L2 for weight rows.
        unsigned long long pol;
        asm volatile("createpolicy.fractional.L2::evict_first.b64 %0, 1.0;"
                     : "=l"(pol));

        // 8 async bulk scatters S->G.
#pragma unroll
        for (int r = 0; r < ROWS_PER_CTA; r++) {
            char* dst = out + (size_t)(base_row + r) * ROW_BYTES;
            asm volatile(
                "cp.async.bulk.global.shared::cta.bulk_group.L2::cache_hint "
                "[%0], [%1], %2, %3;"
                :: "l"(dst), "r"(buf_a + r * ROW_BYTES), "r"((uint32_t)ROW_BYTES),
                   "l"(pol)
                : "memory");
        }
        asm volatile("cp.async.bulk.commit_group;" ::: "memory");
        asm volatile("cp.async.bulk.wait_group 0;" ::: "memory");
    }
}

extern "C" void kernel_launch(void* const* d_in, const int* in_sizes, int n_in,
                              void* d_out, int out_size)
{
    // Select inputs by size: the weight matrix is by far the larger tensor.
    int w_idx = 0, id_idx = 1;
    if (n_in >= 2 && in_sizes[1] > in_sizes[0]) { w_idx = 1; id_idx = 0; }

    const char* w   = (const char*)d_in[w_idx];
    const int*  ids = (const int*)d_in[id_idx];
    char*       out = (char*)d_out;

    const int n_rows = out_size / 1024;              // 32768 rows of 1024 fp32
    const int n_blocks = n_rows / ROWS_PER_CTA;      // 4096

    WordEmbedding_43181601194151_kernel<<<n_blocks, 32>>>(w, ids, out);
}